// round 11
// baseline (speedup 1.0000x reference)
#include <cuda_runtime.h>

// Residual VQ via 3-term bf16 tensor-core MMA (mma.sync.m16n8k16).
// a = hi + lo (hi = round-to-bf16 via integer +0x8000 & mask; lo exact fp32,
// truncated to bf16). dot ~= Ahi.Bhi + Ahi.Blo + Alo.Bhi, error ~3.5e-4 rms.
// Rescue window EPS=2e-2 (>=28 sigma) guarantees any potential flip is
// re-decided by the exact fp64 full rescan -> argmin matches exact reference.
// B's hi/lo bf16 planes precomputed once per stage; exact fp32 codebook values
// for update/rescue are re-read from global (L2-resident).
// Output (float32): x_q [N*128], mean_loss [1], indices [N*S].

#define D        128
#define C        256
#define ROWS     128
#define THREADS  1024
#define NWARP    32
#define MAXGRID  4096
#define EPS_GAP  2e-2f
#define LDA      132            // A row stride (floats)
#define LDB      136            // B row stride (bf16 elems) -> conflict-free frags

__device__ float        g_part[MAXGRID];
__device__ unsigned int g_cnt = 0;

// smem layout (bytes)
#define OFF_A    0                                   // float A[128][132]   67584
#define OFF_BH   67584                               // u16 Bhi[256][136]   69632
#define OFF_BL   137216                              // u16 Blo[256][136]   69632
#define OFF_CN   206848                              // float cnorm[256]     1024
#define OFF_PB1  207872                              // float[1024]          4096
#define OFF_PB2  211968                              // float[1024]          4096
#define OFF_PI1  216064                              // int[1024]            4096
#define OFF_IDX  220160                              // int[128]              512
#define OFF_IALL 220672                              // float[1024]          4096
#define OFF_RED  224768                              // float[32]             128
#define OFF_CNT  224896                              // int (+pad)             32
#define OFF_LIST 224928                              // int[128]              512
#define SMEM_BYTES 225472

#define MMA_BF16(c0,c1,c2,c3,a0,a1,a2,a3,b0,b1) \
    asm volatile("mma.sync.aligned.m16n8k16.row.col.f32.bf16.bf16.f32 " \
                 "{%0,%1,%2,%3},{%4,%5,%6,%7},{%8,%9},{%0,%1,%2,%3};" \
                 : "+f"(c0), "+f"(c1), "+f"(c2), "+f"(c3) \
                 : "r"(a0), "r"(a1), "r"(a2), "r"(a3), "r"(b0), "r"(b1))

// split a float pair into packed bf16x2 (hi) and packed bf16x2 (lo).
// hi = round-to-nearest bf16 (integer round); lo = exact fp32 remainder,
// truncated to bf16 by byte_perm (error 2^-15|a|, absorbed in EPS budget).
__device__ __forceinline__ void split2(float x, float y, unsigned& phi, unsigned& plo) {
    const unsigned h0 = (__float_as_uint(x) + 0x8000u) & 0xFFFF0000u;
    const unsigned h1 = (__float_as_uint(y) + 0x8000u) & 0xFFFF0000u;
    const float l0 = x - __uint_as_float(h0);
    const float l1 = y - __uint_as_float(h1);
    phi = __byte_perm(h0, h1, 0x7632);
    plo = __byte_perm(__float_as_uint(l0), __float_as_uint(l1), 0x7632);
}

__global__ void __launch_bounds__(THREADS, 1)
rvq_kernel(const float* __restrict__ x, const float* __restrict__ cbs,
           float* __restrict__ out, int N, int S)
{
    extern __shared__ char smc[];
    float*          A       = (float*)(smc + OFF_A);
    unsigned short* BH      = (unsigned short*)(smc + OFF_BH);
    unsigned short* BL      = (unsigned short*)(smc + OFF_BL);
    float*          cnorm   = (float*)(smc + OFF_CN);
    float*          pB1     = (float*)(smc + OFF_PB1);
    float*          pB2     = (float*)(smc + OFF_PB2);
    int*            pI1     = (int*)(smc + OFF_PI1);
    int*            sIdx    = (int*)(smc + OFF_IDX);
    float*          sIdxAll = (float*)(smc + OFF_IALL);
    float*          sRed    = (float*)(smc + OFF_RED);
    int*            sCnt    = (int*)(smc + OFF_CNT);
    int*            sList   = (int*)(smc + OFF_LIST);
    __shared__ int sLast;

    const int tid  = threadIdx.x;
    const int lane = tid & 31;
    const int w    = tid >> 5;       // 0..31
    const int g    = lane >> 2;      // mma group (0..7)
    const int t    = lane & 3;       // thread-in-group (0..3)
    const long long rowBase = (long long)blockIdx.x * ROWS;

    const int rt = w & 3;            // row tile: rows [rt*32, rt*32+32)
    const int ct = w >> 2;           // code tile: codes [ct*32, ct*32+32)
    const int arow = rt * 32 + g;

    // ---- load x tile into A: warp w -> rows [4w, 4w+4) ----
    {
        const int r8 = lane >> 3, f = lane & 7;
        const int row = 4 * w + r8;
        #pragma unroll
        for (int j = 0; j < 4; ++j) {
            const int k = j * 32 + f * 4;
            *(float4*)(A + row * LDA + k) =
                *(const float4*)(x + (rowBase + row) * D + k);
        }
    }

    float lsum = 0.f;

    for (int s = 0; s < S; ++s) {
        const float* cbS = cbs + (size_t)s * C * D;
        __syncthreads();             // previous stage done with B planes
        if (tid == 0) *sCnt = 0;

        // ---- codebook stage s -> Bhi/Blo bf16 planes + cnorm ----
        {
            const int r8 = lane >> 3, f = lane & 7;
            #pragma unroll
            for (int i = 0; i < 2; ++i) {
                const int code = 8 * w + 4 * i + r8;
                float psum = 0.f;
                #pragma unroll
                for (int j = 0; j < 4; ++j) {
                    const int k = j * 32 + f * 4;
                    const float4 v = *(const float4*)(cbS + code * D + k);
                    unsigned ph0, pl0, ph1, pl1;
                    split2(v.x, v.y, ph0, pl0);
                    split2(v.z, v.w, ph1, pl1);
                    *(uint2*)(BH + code * LDB + k) = make_uint2(ph0, ph1);
                    *(uint2*)(BL + code * LDB + k) = make_uint2(pl0, pl1);
                    psum += v.x * v.x + v.y * v.y + v.z * v.z + v.w * v.w;
                }
                psum += __shfl_down_sync(0xffffffffu, psum, 4);
                psum += __shfl_down_sync(0xffffffffu, psum, 2);
                psum += __shfl_down_sync(0xffffffffu, psum, 1);
                if (f == 0) cnorm[code] = psum;
            }
        }
        __syncthreads();

        // ---- 3-term bf16 MMA: accurate dots[32 rows][32 codes] per warp ----
        float acc[2][4][4];
        #pragma unroll
        for (int h = 0; h < 2; ++h)
            #pragma unroll
            for (int n = 0; n < 4; ++n)
                #pragma unroll
                for (int q = 0; q < 4; ++q) acc[h][n][q] = 0.f;

        #pragma unroll
        for (int kt = 0; kt < 8; ++kt) {
            const int kb = kt * 16;
            // A fragments: per h, 4 packed pairs: (r0,k0),(r0+8,k0),(r0,k0+8),(r0+8,k0+8)
            unsigned ahi[2][4], alo[2][4];
            #pragma unroll
            for (int h = 0; h < 2; ++h) {
                const int r0 = arow + 16 * h;
                const float2 p0 = *(const float2*)(A +  r0      * LDA + kb + 2 * t);
                const float2 p1 = *(const float2*)(A + (r0 + 8) * LDA + kb + 2 * t);
                const float2 p2 = *(const float2*)(A +  r0      * LDA + kb + 8 + 2 * t);
                const float2 p3 = *(const float2*)(A + (r0 + 8) * LDA + kb + 8 + 2 * t);
                split2(p0.x, p0.y, ahi[h][0], alo[h][0]);
                split2(p1.x, p1.y, ahi[h][1], alo[h][1]);
                split2(p2.x, p2.y, ahi[h][2], alo[h][2]);
                split2(p3.x, p3.y, ahi[h][3], alo[h][3]);
            }
            #pragma unroll
            for (int n = 0; n < 4; ++n) {
                const int code = ct * 32 + n * 8 + g;
                const int bbase = code * LDB + kb + 2 * t;
                const unsigned bh0 = *(const unsigned*)(BH + bbase);
                const unsigned bh1 = *(const unsigned*)(BH + bbase + 8);
                const unsigned bl0 = *(const unsigned*)(BL + bbase);
                const unsigned bl1 = *(const unsigned*)(BL + bbase + 8);
                #pragma unroll
                for (int h = 0; h < 2; ++h) {
                    MMA_BF16(acc[h][n][0], acc[h][n][1], acc[h][n][2], acc[h][n][3],
                             ahi[h][0], ahi[h][1], ahi[h][2], ahi[h][3], bh0, bh1);
                    MMA_BF16(acc[h][n][0], acc[h][n][1], acc[h][n][2], acc[h][n][3],
                             ahi[h][0], ahi[h][1], ahi[h][2], ahi[h][3], bl0, bl1);
                    MMA_BF16(acc[h][n][0], acc[h][n][1], acc[h][n][2], acc[h][n][3],
                             alo[h][0], alo[h][1], alo[h][2], alo[h][3], bh0, bh1);
                }
            }
        }

        // ---- per-(row, code-tile) top-2 partials ----
        #pragma unroll
        for (int h = 0; h < 2; ++h) {
            #pragma unroll
            for (int rr = 0; rr < 2; ++rr) {        // row = arow + 16h + 8rr
                float b1v = 3.4e38f, b2v = 3.4e38f;
                int   i1  = 0;
                #pragma unroll
                for (int n = 0; n < 4; ++n) {
                    const int code0 = ct * 32 + n * 8 + 2 * t;
                    const float s0 = fmaf(-2.f, acc[h][n][rr * 2 + 0], cnorm[code0]);
                    const float s1 = fmaf(-2.f, acc[h][n][rr * 2 + 1], cnorm[code0 + 1]);
                    if (s0 < b1v) { b2v = b1v; b1v = s0; i1 = code0; }
                    else if (s0 < b2v) b2v = s0;
                    if (s1 < b1v) { b2v = b1v; b1v = s1; i1 = code0 + 1; }
                    else if (s1 < b2v) b2v = s1;
                }
                #pragma unroll
                for (int off = 1; off <= 2; off <<= 1) {
                    const float ov1 = __shfl_xor_sync(0xffffffffu, b1v, off);
                    const int   oi  = __shfl_xor_sync(0xffffffffu, i1, off);
                    const float ov2 = __shfl_xor_sync(0xffffffffu, b2v, off);
                    const float m2  = fminf(fmaxf(b1v, ov1), fminf(b2v, ov2));
                    if (ov1 < b1v || (ov1 == b1v && oi < i1)) { b1v = ov1; i1 = oi; }
                    b2v = m2;
                }
                if (t == 0) {
                    const int row = arow + 16 * h + 8 * rr;
                    pB1[row * 8 + ct] = b1v;
                    pB2[row * 8 + ct] = b2v;
                    pI1[row * 8 + ct] = i1;
                }
            }
        }
        __syncthreads();

        // ---- merge 8 code-tile partials per row; nominate fp64 rescans ----
        if (w < 4) {
            const int row = w * 32 + lane;
            float b1v = 3.4e38f, b2v = 3.4e38f;
            int   i1  = 0;
            #pragma unroll
            for (int c = 0; c < 8; ++c) {
                const float ov1 = pB1[row * 8 + c];
                const float ov2 = pB2[row * 8 + c];
                const int   oi  = pI1[row * 8 + c];
                const float m2  = fminf(fmaxf(b1v, ov1), fminf(b2v, ov2));
                if (ov1 < b1v || (ov1 == b1v && oi < i1)) { b1v = ov1; i1 = oi; }
                b2v = m2;
            }
            if (b2v - b1v < EPS_GAP) {
                const int pos = atomicAdd(sCnt, 1);
                sList[pos] = row;
            } else {
                sIdx[row] = i1;
                sIdxAll[row * 8 + s] = (float)i1;
            }
        }
        __syncthreads();

        // ---- fp64 full rescan for near-tie rows (rare; exact fp32 from global) ----
        {
            const int cnt = *sCnt;
            for (int e = w; e < cnt; e += NWARP) {
                const int row = sList[e];
                double d1 = 1e300; int di = 0x7fffffff;
                #pragma unroll
                for (int cc = 0; cc < 8; ++cc) {
                    const int code = cc * 32 + lane;
                    const float* Bc  = cbS + code * D;
                    const float* Arf = A + row * LDA;
                    double dsum = 0.0;
                    for (int k = 0; k < D; ++k) {
                        const double df = (double)Arf[k] - (double)Bc[k];
                        dsum = fma(df, df, dsum);
                    }
                    if (dsum < d1 || (dsum == d1 && code < di)) { d1 = dsum; di = code; }
                }
                #pragma unroll
                for (int off = 16; off; off >>= 1) {
                    const double ov = __shfl_xor_sync(0xffffffffu, d1, off);
                    const int    oi = __shfl_xor_sync(0xffffffffu, di, off);
                    if (ov < d1 || (ov == d1 && oi < di)) { d1 = ov; di = oi; }
                }
                if (lane == 0) {
                    sIdx[row] = di;
                    sIdxAll[row * 8 + s] = (float)di;
                }
            }
        }
        __syncthreads();

        // ---- residual update + loss (exact fp32 codebook from global/L2) ----
        {
            const int r8 = lane >> 3, f = lane & 7;
            const int row = 4 * w + r8;
            const int idx = sIdx[row];
            #pragma unroll
            for (int j = 0; j < 4; ++j) {
                const int k = j * 32 + f * 4;
                float4 rv = *(const float4*)(A + row * LDA + k);
                const float4 cv = *(const float4*)(cbS + idx * D + k);
                rv.x -= cv.x; rv.y -= cv.y; rv.z -= cv.z; rv.w -= cv.w;
                *(float4*)(A + row * LDA + k) = rv;
                lsum += rv.x * rv.x + rv.y * rv.y + rv.z * rv.z + rv.w * rv.w;
            }
        }
    }
    __syncthreads();

    // ---- x_q = x - final residual ----
    {
        const int r8 = lane >> 3, f = lane & 7;
        const int row = 4 * w + r8;
        #pragma unroll
        for (int j = 0; j < 4; ++j) {
            const int k = j * 32 + f * 4;
            const float4 xv = *(const float4*)(x + (rowBase + row) * D + k);
            const float4 rv = *(const float4*)(A + row * LDA + k);
            float4 o;
            o.x = xv.x - rv.x; o.y = xv.y - rv.y;
            o.z = xv.z - rv.z; o.w = xv.w - rv.w;
            *(float4*)(out + (rowBase + row) * D + k) = o;
        }
    }

    // ---- indices (float) ----
    float* oIdx = out + (size_t)N * D + 1;
    for (int e = tid; e < ROWS * S; e += THREADS) {
        const int row = e / S, st = e % S;
        oIdx[(rowBase + row) * S + st] = sIdxAll[row * 8 + st];
    }

    // ---- per-CTA loss partial + last-CTA deterministic reduce ----
    #pragma unroll
    for (int off = 16; off; off >>= 1)
        lsum += __shfl_down_sync(0xffffffffu, lsum, off);
    if (lane == 0) sRed[w] = lsum;
    __syncthreads();
    if (tid == 0) {
        float tt = 0.f;
        #pragma unroll
        for (int i = 0; i < NWARP; ++i) tt += sRed[i];
        g_part[blockIdx.x] = tt;
        __threadfence();
        const unsigned ticket = atomicAdd(&g_cnt, 1u);
        sLast = (ticket == (unsigned)gridDim.x - 1u) ? 1 : 0;
    }
    __syncthreads();

    if (sLast) {
        __threadfence();
        const int nPart = gridDim.x;
        float ssum = 0.f;
        for (int i = tid; i < nPart; i += THREADS) ssum += g_part[i];
        #pragma unroll
        for (int off = 16; off; off >>= 1)
            ssum += __shfl_down_sync(0xffffffffu, ssum, off);
        if (lane == 0) sRed[w] = ssum;
        __syncthreads();
        if (tid == 0) {
            float tt = 0.f;
            #pragma unroll
            for (int i = 0; i < NWARP; ++i) tt += sRed[i];
            const float scale = 2.f / ((float)S * (float)N * (float)D);
            out[(size_t)N * D] = tt * scale;
            g_cnt = 0;                   // reset for next graph replay
        }
    }
}

extern "C" void kernel_launch(void* const* d_in, const int* in_sizes, int n_in,
                              void* d_out, int out_size)
{
    const float* x   = (const float*)d_in[0];
    const float* cbs = (const float*)d_in[1];
    float* out = (float*)d_out;

    const int N = in_sizes[0] / D;              // 262144
    const int S = in_sizes[1] / (C * D);        // 4
    const int nBlocks = N / ROWS;               // 2048

    cudaFuncSetAttribute(rvq_kernel, cudaFuncAttributeMaxDynamicSharedMemorySize,
                         SMEM_BYTES);
    rvq_kernel<<<nBlocks, THREADS, SMEM_BYTES>>>(x, cbs, out, N, S);
}

// round 12
// speedup vs baseline: 1.0184x; 1.0184x over previous
#include <cuda_runtime.h>

// Residual VQ via 3-term bf16 tensor-core MMA (mma.sync.m16n8k16).
// a = hi + lo (hi = round-to-bf16; lo exact fp32 remainder, truncated to bf16:
// error ~2^-18|a|, negligible). dot ~= Ahi.Bhi + Ahi.Blo + Alo.Bhi.
// Rescue window EPS=2e-2 (~50x the score error) -> any potential flip is
// re-decided by the exact fp64 full rescan -> argmin matches exact reference.
// LDA=136: 64-bit A fragment loads are bank-conflict-free (8g+2t pattern).
// Output (float32): x_q [N*128], mean_loss [1], indices [N*S].

#define D        128
#define C        256
#define ROWS     128
#define THREADS  1024
#define NWARP    32
#define MAXGRID  4096
#define EPS_GAP  2e-2f
#define LDA      136            // A row stride (floats) — conflict-free pair loads
#define LDB      136            // B row stride (bf16 elems) — conflict-free frags

__device__ float        g_part[MAXGRID];
__device__ unsigned int g_cnt = 0;

// smem layout (bytes)
#define OFF_A    0                                   // float A[128][136]   69632
#define OFF_BH   69632                               // u16 Bhi[256][136]   69632
#define OFF_BL   139264                              // u16 Blo[256][136]   69632
#define OFF_CN   208896                              // float cnorm[256]     1024
#define OFF_PB1  209920                              // float[1024]          4096
#define OFF_PB2  214016                              // float[1024]          4096
#define OFF_PI1  218112                              // int[1024]            4096
#define OFF_IDX  222208                              // int[128]              512
#define OFF_IALL 222720                              // float[1024]          4096
#define OFF_RED  226816                              // float[32]             128
#define OFF_CNT  226944                              // int (+pad)             32
#define OFF_LIST 226976                              // int[128]              512
#define SMEM_BYTES 227488

#define MMA_BF16(c0,c1,c2,c3,a0,a1,a2,a3,b0,b1) \
    asm volatile("mma.sync.aligned.m16n8k16.row.col.f32.bf16.bf16.f32 " \
                 "{%0,%1,%2,%3},{%4,%5,%6,%7},{%8,%9},{%0,%1,%2,%3};" \
                 : "+f"(c0), "+f"(c1), "+f"(c2), "+f"(c3) \
                 : "r"(a0), "r"(a1), "r"(a2), "r"(a3), "r"(b0), "r"(b1))

// split a float pair into packed bf16x2 (hi) and packed bf16x2 (lo).
__device__ __forceinline__ void split2(float x, float y, unsigned& phi, unsigned& plo) {
    const unsigned h0 = (__float_as_uint(x) + 0x8000u) & 0xFFFF0000u;
    const unsigned h1 = (__float_as_uint(y) + 0x8000u) & 0xFFFF0000u;
    const float l0 = x - __uint_as_float(h0);
    const float l1 = y - __uint_as_float(h1);
    phi = __byte_perm(h0, h1, 0x7632);
    plo = __byte_perm(__float_as_uint(l0), __float_as_uint(l1), 0x7632);
}

__global__ void __launch_bounds__(THREADS, 1)
rvq_kernel(const float* __restrict__ x, const float* __restrict__ cbs,
           float* __restrict__ out, int N, int S)
{
    extern __shared__ char smc[];
    float*          A       = (float*)(smc + OFF_A);
    unsigned short* BH      = (unsigned short*)(smc + OFF_BH);
    unsigned short* BL      = (unsigned short*)(smc + OFF_BL);
    float*          cnorm   = (float*)(smc + OFF_CN);
    float*          pB1     = (float*)(smc + OFF_PB1);
    float*          pB2     = (float*)(smc + OFF_PB2);
    int*            pI1     = (int*)(smc + OFF_PI1);
    int*            sIdx    = (int*)(smc + OFF_IDX);
    float*          sIdxAll = (float*)(smc + OFF_IALL);
    float*          sRed    = (float*)(smc + OFF_RED);
    int*            sCnt    = (int*)(smc + OFF_CNT);
    int*            sList   = (int*)(smc + OFF_LIST);
    __shared__ int sLast;

    const int tid  = threadIdx.x;
    const int lane = tid & 31;
    const int w    = tid >> 5;       // 0..31
    const int g    = lane >> 2;      // mma group (0..7)
    const int t    = lane & 3;       // thread-in-group (0..3)
    const long long rowBase = (long long)blockIdx.x * ROWS;

    const int rt = w & 3;            // row tile: rows [rt*32, rt*32+32)
    const int ct = w >> 2;           // code tile: codes [ct*32, ct*32+32)
    const int arow = rt * 32 + g;

    // ---- load x tile into A: warp w -> rows [4w, 4w+4) ----
    {
        const int r8 = lane >> 3, f = lane & 7;
        const int row = 4 * w + r8;
        #pragma unroll
        for (int j = 0; j < 4; ++j) {
            const int k = j * 32 + f * 4;
            *(float4*)(A + row * LDA + k) =
                *(const float4*)(x + (rowBase + row) * D + k);
        }
    }

    float lsum = 0.f;

    for (int s = 0; s < S; ++s) {
        const float* cbS = cbs + (size_t)s * C * D;
        __syncthreads();             // previous stage done with B planes
        if (tid == 0) *sCnt = 0;

        // ---- codebook stage s -> Bhi/Blo bf16 planes + cnorm ----
        {
            const int r8 = lane >> 3, f = lane & 7;
            #pragma unroll
            for (int i = 0; i < 2; ++i) {
                const int code = 8 * w + 4 * i + r8;
                float psum = 0.f;
                #pragma unroll
                for (int j = 0; j < 4; ++j) {
                    const int k = j * 32 + f * 4;
                    const float4 v = *(const float4*)(cbS + code * D + k);
                    unsigned ph0, pl0, ph1, pl1;
                    split2(v.x, v.y, ph0, pl0);
                    split2(v.z, v.w, ph1, pl1);
                    *(uint2*)(BH + code * LDB + k) = make_uint2(ph0, ph1);
                    *(uint2*)(BL + code * LDB + k) = make_uint2(pl0, pl1);
                    psum += v.x * v.x + v.y * v.y + v.z * v.z + v.w * v.w;
                }
                psum += __shfl_down_sync(0xffffffffu, psum, 4);
                psum += __shfl_down_sync(0xffffffffu, psum, 2);
                psum += __shfl_down_sync(0xffffffffu, psum, 1);
                if (f == 0) cnorm[code] = psum;
            }
        }
        __syncthreads();

        // ---- 3-term bf16 MMA: accurate dots[32 rows][32 codes] per warp ----
        float acc[2][4][4];
        #pragma unroll
        for (int h = 0; h < 2; ++h)
            #pragma unroll
            for (int n = 0; n < 4; ++n)
                #pragma unroll
                for (int q = 0; q < 4; ++q) acc[h][n][q] = 0.f;

        #pragma unroll 2
        for (int kt = 0; kt < 8; ++kt) {
            const int kb = kt * 16;
            // A fragments: per h, packed pairs (r0,k),(r0+8,k),(r0,k+8),(r0+8,k+8)
            unsigned ahi[2][4], alo[2][4];
            #pragma unroll
            for (int h = 0; h < 2; ++h) {
                const int r0 = arow + 16 * h;
                const float2 p0 = *(const float2*)(A +  r0      * LDA + kb + 2 * t);
                const float2 p1 = *(const float2*)(A + (r0 + 8) * LDA + kb + 2 * t);
                const float2 p2 = *(const float2*)(A +  r0      * LDA + kb + 8 + 2 * t);
                const float2 p3 = *(const float2*)(A + (r0 + 8) * LDA + kb + 8 + 2 * t);
                split2(p0.x, p0.y, ahi[h][0], alo[h][0]);
                split2(p1.x, p1.y, ahi[h][1], alo[h][1]);
                split2(p2.x, p2.y, ahi[h][2], alo[h][2]);
                split2(p3.x, p3.y, ahi[h][3], alo[h][3]);
            }
            #pragma unroll
            for (int n = 0; n < 4; ++n) {
                const int code = ct * 32 + n * 8 + g;
                const int bbase = code * LDB + kb + 2 * t;
                const unsigned bh0 = *(const unsigned*)(BH + bbase);
                const unsigned bh1 = *(const unsigned*)(BH + bbase + 8);
                const unsigned bl0 = *(const unsigned*)(BL + bbase);
                const unsigned bl1 = *(const unsigned*)(BL + bbase + 8);
                #pragma unroll
                for (int h = 0; h < 2; ++h) {
                    MMA_BF16(acc[h][n][0], acc[h][n][1], acc[h][n][2], acc[h][n][3],
                             ahi[h][0], ahi[h][1], ahi[h][2], ahi[h][3], bh0, bh1);
                    MMA_BF16(acc[h][n][0], acc[h][n][1], acc[h][n][2], acc[h][n][3],
                             ahi[h][0], ahi[h][1], ahi[h][2], ahi[h][3], bl0, bl1);
                    MMA_BF16(acc[h][n][0], acc[h][n][1], acc[h][n][2], acc[h][n][3],
                             alo[h][0], alo[h][1], alo[h][2], alo[h][3], bh0, bh1);
                }
            }
        }

        // ---- per-(row, code-tile) top-2 partials ----
        #pragma unroll
        for (int h = 0; h < 2; ++h) {
            #pragma unroll
            for (int rr = 0; rr < 2; ++rr) {        // row = arow + 16h + 8rr
                float b1v = 3.4e38f, b2v = 3.4e38f;
                int   i1  = 0;
                #pragma unroll
                for (int n = 0; n < 4; ++n) {
                    const int code0 = ct * 32 + n * 8 + 2 * t;
                    const float s0 = fmaf(-2.f, acc[h][n][rr * 2 + 0], cnorm[code0]);
                    const float s1 = fmaf(-2.f, acc[h][n][rr * 2 + 1], cnorm[code0 + 1]);
                    if (s0 < b1v) { b2v = b1v; b1v = s0; i1 = code0; }
                    else if (s0 < b2v) b2v = s0;
                    if (s1 < b1v) { b2v = b1v; b1v = s1; i1 = code0 + 1; }
                    else if (s1 < b2v) b2v = s1;
                }
                #pragma unroll
                for (int off = 1; off <= 2; off <<= 1) {
                    const float ov1 = __shfl_xor_sync(0xffffffffu, b1v, off);
                    const int   oi  = __shfl_xor_sync(0xffffffffu, i1, off);
                    const float ov2 = __shfl_xor_sync(0xffffffffu, b2v, off);
                    const float m2  = fminf(fmaxf(b1v, ov1), fminf(b2v, ov2));
                    if (ov1 < b1v || (ov1 == b1v && oi < i1)) { b1v = ov1; i1 = oi; }
                    b2v = m2;
                }
                if (t == 0) {
                    const int row = arow + 16 * h + 8 * rr;
                    pB1[row * 8 + ct] = b1v;
                    pB2[row * 8 + ct] = b2v;
                    pI1[row * 8 + ct] = i1;
                }
            }
        }
        __syncthreads();

        // ---- merge 8 code-tile partials per row; nominate fp64 rescans ----
        if (w < 4) {
            const int row = w * 32 + lane;
            float b1v = 3.4e38f, b2v = 3.4e38f;
            int   i1  = 0;
            #pragma unroll
            for (int c = 0; c < 8; ++c) {
                const float ov1 = pB1[row * 8 + c];
                const float ov2 = pB2[row * 8 + c];
                const int   oi  = pI1[row * 8 + c];
                const float m2  = fminf(fmaxf(b1v, ov1), fminf(b2v, ov2));
                if (ov1 < b1v || (ov1 == b1v && oi < i1)) { b1v = ov1; i1 = oi; }
                b2v = m2;
            }
            if (b2v - b1v < EPS_GAP) {
                const int pos = atomicAdd(sCnt, 1);
                sList[pos] = row;
            } else {
                sIdx[row] = i1;
                sIdxAll[row * 8 + s] = (float)i1;
            }
        }
        __syncthreads();

        // ---- fp64 full rescan for near-tie rows (rare; exact fp32 from global) ----
        {
            const int cnt = *sCnt;
            for (int e = w; e < cnt; e += NWARP) {
                const int row = sList[e];
                double d1 = 1e300; int di = 0x7fffffff;
                #pragma unroll
                for (int cc = 0; cc < 8; ++cc) {
                    const int code = cc * 32 + lane;
                    const float* Bc  = cbS + code * D;
                    const float* Arf = A + row * LDA;
                    double dsum = 0.0;
                    for (int k = 0; k < D; ++k) {
                        const double df = (double)Arf[k] - (double)Bc[k];
                        dsum = fma(df, df, dsum);
                    }
                    if (dsum < d1 || (dsum == d1 && code < di)) { d1 = dsum; di = code; }
                }
                #pragma unroll
                for (int off = 16; off; off >>= 1) {
                    const double ov = __shfl_xor_sync(0xffffffffu, d1, off);
                    const int    oi = __shfl_xor_sync(0xffffffffu, di, off);
                    if (ov < d1 || (ov == d1 && oi < di)) { d1 = ov; di = oi; }
                }
                if (lane == 0) {
                    sIdx[row] = di;
                    sIdxAll[row * 8 + s] = (float)di;
                }
            }
        }
        __syncthreads();

        // ---- residual update + loss (exact fp32 codebook from global/L2) ----
        {
            const int r8 = lane >> 3, f = lane & 7;
            const int row = 4 * w + r8;
            const int idx = sIdx[row];
            #pragma unroll
            for (int j = 0; j < 4; ++j) {
                const int k = j * 32 + f * 4;
                float4 rv = *(const float4*)(A + row * LDA + k);
                const float4 cv = *(const float4*)(cbS + idx * D + k);
                rv.x -= cv.x; rv.y -= cv.y; rv.z -= cv.z; rv.w -= cv.w;
                *(float4*)(A + row * LDA + k) = rv;
                lsum += rv.x * rv.x + rv.y * rv.y + rv.z * rv.z + rv.w * rv.w;
            }
        }
    }
    __syncthreads();

    // ---- x_q = x - final residual ----
    {
        const int r8 = lane >> 3, f = lane & 7;
        const int row = 4 * w + r8;
        #pragma unroll
        for (int j = 0; j < 4; ++j) {
            const int k = j * 32 + f * 4;
            const float4 xv = *(const float4*)(x + (rowBase + row) * D + k);
            const float4 rv = *(const float4*)(A + row * LDA + k);
            float4 o;
            o.x = xv.x - rv.x; o.y = xv.y - rv.y;
            o.z = xv.z - rv.z; o.w = xv.w - rv.w;
            *(float4*)(out + (rowBase + row) * D + k) = o;
        }
    }

    // ---- indices (float) ----
    float* oIdx = out + (size_t)N * D + 1;
    for (int e = tid; e < ROWS * S; e += THREADS) {
        const int row = e / S, st = e % S;
        oIdx[(rowBase + row) * S + st] = sIdxAll[row * 8 + st];
    }

    // ---- per-CTA loss partial + last-CTA deterministic reduce ----
    #pragma unroll
    for (int off = 16; off; off >>= 1)
        lsum += __shfl_down_sync(0xffffffffu, lsum, off);
    if (lane == 0) sRed[w] = lsum;
    __syncthreads();
    if (tid == 0) {
        float tt = 0.f;
        #pragma unroll
        for (int i = 0; i < NWARP; ++i) tt += sRed[i];
        g_part[blockIdx.x] = tt;
        __threadfence();
        const unsigned ticket = atomicAdd(&g_cnt, 1u);
        sLast = (ticket == (unsigned)gridDim.x - 1u) ? 1 : 0;
    }
    __syncthreads();

    if (sLast) {
        __threadfence();
        const int nPart = gridDim.x;
        float ssum = 0.f;
        for (int i = tid; i < nPart; i += THREADS) ssum += g_part[i];
        #pragma unroll
        for (int off = 16; off; off >>= 1)
            ssum += __shfl_down_sync(0xffffffffu, ssum, off);
        if (lane == 0) sRed[w] = ssum;
        __syncthreads();
        if (tid == 0) {
            float tt = 0.f;
            #pragma unroll
            for (int i = 0; i < NWARP; ++i) tt += sRed[i];
            const float scale = 2.f / ((float)S * (float)N * (float)D);
            out[(size_t)N * D] = tt * scale;
            g_cnt = 0;                   // reset for next graph replay
        }
    }
}

extern "C" void kernel_launch(void* const* d_in, const int* in_sizes, int n_in,
                              void* d_out, int out_size)
{
    const float* x   = (const float*)d_in[0];
    const float* cbs = (const float*)d_in[1];
    float* out = (float*)d_out;

    const int N = in_sizes[0] / D;              // 262144
    const int S = in_sizes[1] / (C * D);        // 4
    const int nBlocks = N / ROWS;               // 2048

    cudaFuncSetAttribute(rvq_kernel, cudaFuncAttributeMaxDynamicSharedMemorySize,
                         SMEM_BYTES);
    rvq_kernel<<<nBlocks, THREADS, SMEM_BYTES>>>(x, cbs, out, N, S);
}

// round 13
// speedup vs baseline: 1.8466x; 1.8132x over previous
#include <cuda_runtime.h>

// Residual VQ via 3xTF32 tensor-core MMA (mma.sync.m16n8k8, mask split).
// hi = x & 0xFFFFE000 (exactly tf32), lo = x - hi (exact fp32, HW-truncated).
// MMAs issued TERM-MAJOR per k-step: all 8 acc tiles get term0 (hi*hi), then
// term1 (hi*lo), then term2 (lo*hi) -> same-accumulator reuse distance is 8
// MMAs, hiding the HMMA accumulator RAW latency that serialized R10.
// Rescue: fp64 full rescan when top-2 gap < 2e-3 (>=4x worst-case score err),
// 4 independent fp64 accumulators to break the DFMA chain.
// Output (float32): x_q [N*128], mean_loss [1], indices [N*S].

#define D        128
#define C        256
#define ROWS     128
#define THREADS  1024
#define NWARP    32
#define MAXGRID  4096
#define EPS_GAP  2e-3f
#define LDA      132            // padded row stride (floats)

__device__ float        g_part[MAXGRID];
__device__ unsigned int g_cnt = 0;

// dynamic smem (floats)
#define OFF_A    0
#define OFF_B    (OFF_A + ROWS*LDA)
#define OFF_CN   (OFF_B + C*LDA)
#define OFF_PB1  (OFF_CN + 256)
#define OFF_PB2  (OFF_PB1 + 1024)
#define OFF_PI1  (OFF_PB2 + 1024)
#define OFF_IDX  (OFF_PI1 + 1024)
#define OFF_IALL (OFF_IDX + 128)
#define OFF_RED  (OFF_IALL + 128*8)
#define OFF_CNT  (OFF_RED + 32)
#define OFF_LIST (OFF_CNT + 1)
#define SMEM_FLOATS (OFF_LIST + 128)
#define SMEM_BYTES  (SMEM_FLOATS * 4 + 64)

#define MMA_TF32(c0,c1,c2,c3,a0,a1,a2,a3,b0,b1) \
    asm volatile("mma.sync.aligned.m16n8k8.row.col.f32.tf32.tf32.f32 " \
                 "{%0,%1,%2,%3},{%4,%5,%6,%7},{%8,%9},{%0,%1,%2,%3};" \
                 : "+f"(c0), "+f"(c1), "+f"(c2), "+f"(c3) \
                 : "r"(a0), "r"(a1), "r"(a2), "r"(a3), "r"(b0), "r"(b1))

__device__ __forceinline__ void split_tf32(float x, unsigned& hi, unsigned& lo) {
    hi = __float_as_uint(x) & 0xFFFFE000u;
    lo = __float_as_uint(x - __uint_as_float(hi));
}

__global__ void __launch_bounds__(THREADS, 1)
rvq_kernel(const float* __restrict__ x, const float* __restrict__ cbs,
           float* __restrict__ out, int N, int S)
{
    extern __shared__ float sm[];
    float* A       = sm + OFF_A;            // residual [row][k], stride 132
    float* B       = sm + OFF_B;            // codebook [code][k], stride 132
    float* cnorm   = sm + OFF_CN;
    float* pB1     = sm + OFF_PB1;          // partial best  [row*8 + ct]
    float* pB2     = sm + OFF_PB2;          // partial 2nd   [row*8 + ct]
    int*   pI1     = (int*)(sm + OFF_PI1);  // partial index [row*8 + ct]
    int*   sIdx    = (int*)(sm + OFF_IDX);
    float* sIdxAll = sm + OFF_IALL;
    float* sRed    = sm + OFF_RED;
    int*   sCnt    = (int*)(sm + OFF_CNT);
    int*   sList   = (int*)(sm + OFF_LIST);
    __shared__ int sLast;

    const int tid  = threadIdx.x;
    const int lane = tid & 31;
    const int w    = tid >> 5;       // 0..31
    const int g    = lane >> 2;      // mma group (0..7)
    const int t    = lane & 3;       // thread-in-group (0..3)
    const long long rowBase = (long long)blockIdx.x * ROWS;

    const int rt = w & 3;            // row tile: rows [rt*32, rt*32+32)
    const int ct = w >> 2;           // code tile: codes [ct*32, ct*32+32)
    const int arow = rt * 32 + g;

    // ---- load x tile into A: warp w -> rows [4w, 4w+4) ----
    {
        const int r8 = lane >> 3, f = lane & 7;
        const int row = 4 * w + r8;
        #pragma unroll
        for (int j = 0; j < 4; ++j) {
            const int k = j * 32 + f * 4;
            *(float4*)(A + row * LDA + k) =
                *(const float4*)(x + (rowBase + row) * D + k);
        }
    }

    float lsum = 0.f;

    for (int s = 0; s < S; ++s) {
        __syncthreads();             // previous stage done with B
        if (tid == 0) *sCnt = 0;

        // ---- codebook stage s -> B + cnorm (fixed-tree reduce over 8 lanes) ----
        {
            const float* cb = cbs + (size_t)s * C * D;
            const int r8 = lane >> 3, f = lane & 7;
            #pragma unroll
            for (int i = 0; i < 2; ++i) {
                const int code = 8 * w + 4 * i + r8;
                float psum = 0.f;
                #pragma unroll
                for (int j = 0; j < 4; ++j) {
                    const int k = j * 32 + f * 4;
                    const float4 v = *(const float4*)(cb + code * D + k);
                    *(float4*)(B + code * LDA + k) = v;
                    psum += v.x * v.x + v.y * v.y + v.z * v.z + v.w * v.w;
                }
                psum += __shfl_down_sync(0xffffffffu, psum, 4);
                psum += __shfl_down_sync(0xffffffffu, psum, 2);
                psum += __shfl_down_sync(0xffffffffu, psum, 1);
                if (f == 0) cnorm[code] = psum;
            }
        }
        __syncthreads();

        // ---- 3xTF32 MMA, term-major issue order ----
        float acc[2][4][4];
        #pragma unroll
        for (int h = 0; h < 2; ++h)
            #pragma unroll
            for (int n = 0; n < 4; ++n)
                #pragma unroll
                for (int q = 0; q < 4; ++q) acc[h][n][q] = 0.f;

        #pragma unroll 2
        for (int kt = 0; kt < 16; ++kt) {
            const int kb = kt * 8;
            unsigned afh[2][4], afl[2][4];
            #pragma unroll
            for (int h = 0; h < 2; ++h) {
                const int r0 = arow + 16 * h;
                split_tf32(A[ r0      * LDA + kb + t],     afh[h][0], afl[h][0]);
                split_tf32(A[(r0 + 8) * LDA + kb + t],     afh[h][1], afl[h][1]);
                split_tf32(A[ r0      * LDA + kb + t + 4], afh[h][2], afl[h][2]);
                split_tf32(A[(r0 + 8) * LDA + kb + t + 4], afh[h][3], afl[h][3]);
            }
            // term 0: Ahi x Bhi  (8 MMAs, all distinct accumulators)
            #pragma unroll
            for (int n = 0; n < 4; ++n) {
                const int code = ct * 32 + n * 8 + g;
                const unsigned b0 = __float_as_uint(B[code * LDA + kb + t])     & 0xFFFFE000u;
                const unsigned b1 = __float_as_uint(B[code * LDA + kb + t + 4]) & 0xFFFFE000u;
                MMA_TF32(acc[0][n][0], acc[0][n][1], acc[0][n][2], acc[0][n][3],
                         afh[0][0], afh[0][1], afh[0][2], afh[0][3], b0, b1);
                MMA_TF32(acc[1][n][0], acc[1][n][1], acc[1][n][2], acc[1][n][3],
                         afh[1][0], afh[1][1], afh[1][2], afh[1][3], b0, b1);
            }
            // term 1: Ahi x Blo
            #pragma unroll
            for (int n = 0; n < 4; ++n) {
                const int code = ct * 32 + n * 8 + g;
                unsigned bh0, bl0, bh1, bl1;
                split_tf32(B[code * LDA + kb + t],     bh0, bl0);
                split_tf32(B[code * LDA + kb + t + 4], bh1, bl1);
                MMA_TF32(acc[0][n][0], acc[0][n][1], acc[0][n][2], acc[0][n][3],
                         afh[0][0], afh[0][1], afh[0][2], afh[0][3], bl0, bl1);
                MMA_TF32(acc[1][n][0], acc[1][n][1], acc[1][n][2], acc[1][n][3],
                         afh[1][0], afh[1][1], afh[1][2], afh[1][3], bl0, bl1);
            }
            // term 2: Alo x Bhi
            #pragma unroll
            for (int n = 0; n < 4; ++n) {
                const int code = ct * 32 + n * 8 + g;
                const unsigned b0 = __float_as_uint(B[code * LDA + kb + t])     & 0xFFFFE000u;
                const unsigned b1 = __float_as_uint(B[code * LDA + kb + t + 4]) & 0xFFFFE000u;
                MMA_TF32(acc[0][n][0], acc[0][n][1], acc[0][n][2], acc[0][n][3],
                         afl[0][0], afl[0][1], afl[0][2], afl[0][3], b0, b1);
                MMA_TF32(acc[1][n][0], acc[1][n][1], acc[1][n][2], acc[1][n][3],
                         afl[1][0], afl[1][1], afl[1][2], afl[1][3], b0, b1);
            }
        }

        // ---- per-(row, code-tile) top-2 partials ----
        #pragma unroll
        for (int h = 0; h < 2; ++h) {
            #pragma unroll
            for (int rr = 0; rr < 2; ++rr) {        // row = arow + 16h + 8rr
                float b1v = 3.4e38f, b2v = 3.4e38f;
                int   i1  = 0;
                #pragma unroll
                for (int n = 0; n < 4; ++n) {
                    const int code0 = ct * 32 + n * 8 + 2 * t;
                    const float s0 = fmaf(-2.f, acc[h][n][rr * 2 + 0], cnorm[code0]);
                    const float s1 = fmaf(-2.f, acc[h][n][rr * 2 + 1], cnorm[code0 + 1]);
                    if (s0 < b1v) { b2v = b1v; b1v = s0; i1 = code0; }
                    else if (s0 < b2v) b2v = s0;
                    if (s1 < b1v) { b2v = b1v; b1v = s1; i1 = code0 + 1; }
                    else if (s1 < b2v) b2v = s1;
                }
                #pragma unroll
                for (int off = 1; off <= 2; off <<= 1) {
                    const float ov1 = __shfl_xor_sync(0xffffffffu, b1v, off);
                    const int   oi  = __shfl_xor_sync(0xffffffffu, i1, off);
                    const float ov2 = __shfl_xor_sync(0xffffffffu, b2v, off);
                    const float m2  = fminf(fmaxf(b1v, ov1), fminf(b2v, ov2));
                    if (ov1 < b1v || (ov1 == b1v && oi < i1)) { b1v = ov1; i1 = oi; }
                    b2v = m2;
                }
                if (t == 0) {
                    const int row = arow + 16 * h + 8 * rr;
                    pB1[row * 8 + ct] = b1v;
                    pB2[row * 8 + ct] = b2v;
                    pI1[row * 8 + ct] = i1;
                }
            }
        }
        __syncthreads();

        // ---- merge 8 code-tile partials per row; nominate fp64 rescans ----
        if (w < 4) {
            const int row = w * 32 + lane;
            float b1v = 3.4e38f, b2v = 3.4e38f;
            int   i1  = 0;
            #pragma unroll
            for (int c = 0; c < 8; ++c) {
                const float ov1 = pB1[row * 8 + c];
                const float ov2 = pB2[row * 8 + c];
                const int   oi  = pI1[row * 8 + c];
                const float m2  = fminf(fmaxf(b1v, ov1), fminf(b2v, ov2));
                if (ov1 < b1v || (ov1 == b1v && oi < i1)) { b1v = ov1; i1 = oi; }
                b2v = m2;
            }
            if (b2v - b1v < EPS_GAP) {
                const int pos = atomicAdd(sCnt, 1);
                sList[pos] = row;
            } else {
                sIdx[row] = i1;
                sIdxAll[row * 8 + s] = (float)i1;
            }
        }
        __syncthreads();

        // ---- fp64 full rescan for near-tie rows (rare; 4-way ILP chain) ----
        {
            const int cnt = *sCnt;
            for (int e = w; e < cnt; e += NWARP) {
                const int row = sList[e];
                double d1 = 1e300; int di = 0x7fffffff;
                #pragma unroll
                for (int cc = 0; cc < 8; ++cc) {
                    const int code = cc * 32 + lane;
                    const float* Bc  = B + code * LDA;
                    const float* Arf = A + row * LDA;
                    double q0 = 0.0, q1 = 0.0, q2 = 0.0, q3 = 0.0;
                    for (int k = 0; k < D; k += 4) {
                        const double f0 = (double)Arf[k]     - (double)Bc[k];
                        const double f1 = (double)Arf[k + 1] - (double)Bc[k + 1];
                        const double f2 = (double)Arf[k + 2] - (double)Bc[k + 2];
                        const double f3 = (double)Arf[k + 3] - (double)Bc[k + 3];
                        q0 = fma(f0, f0, q0);
                        q1 = fma(f1, f1, q1);
                        q2 = fma(f2, f2, q2);
                        q3 = fma(f3, f3, q3);
                    }
                    const double dsum = ((q0 + q1) + q2) + q3;
                    if (dsum < d1 || (dsum == d1 && code < di)) { d1 = dsum; di = code; }
                }
                #pragma unroll
                for (int off = 16; off; off >>= 1) {
                    const double ov = __shfl_xor_sync(0xffffffffu, d1, off);
                    const int    oi = __shfl_xor_sync(0xffffffffu, di, off);
                    if (ov < d1 || (ov == d1 && oi < di)) { d1 = ov; di = oi; }
                }
                if (lane == 0) {
                    sIdx[row] = di;
                    sIdxAll[row * 8 + s] = (float)di;
                }
            }
        }
        __syncthreads();

        // ---- residual update + loss: warp w -> rows [4w, 4w+4) ----
        {
            const int r8 = lane >> 3, f = lane & 7;
            const int row = 4 * w + r8;
            const int idx = sIdx[row];
            #pragma unroll
            for (int j = 0; j < 4; ++j) {
                const int k = j * 32 + f * 4;
                float4 rv = *(const float4*)(A + row * LDA + k);
                const float4 cv = *(const float4*)(B + idx * LDA + k);
                rv.x -= cv.x; rv.y -= cv.y; rv.z -= cv.z; rv.w -= cv.w;
                *(float4*)(A + row * LDA + k) = rv;
                lsum += rv.x * rv.x + rv.y * rv.y + rv.z * rv.z + rv.w * rv.w;
            }
        }
    }
    __syncthreads();

    // ---- x_q = x - final residual ----
    {
        const int r8 = lane >> 3, f = lane & 7;
        const int row = 4 * w + r8;
        #pragma unroll
        for (int j = 0; j < 4; ++j) {
            const int k = j * 32 + f * 4;
            const float4 xv = *(const float4*)(x + (rowBase + row) * D + k);
            const float4 rv = *(const float4*)(A + row * LDA + k);
            float4 o;
            o.x = xv.x - rv.x; o.y = xv.y - rv.y;
            o.z = xv.z - rv.z; o.w = xv.w - rv.w;
            *(float4*)(out + (rowBase + row) * D + k) = o;
        }
    }

    // ---- indices (float) ----
    float* oIdx = out + (size_t)N * D + 1;
    for (int e = tid; e < ROWS * S; e += THREADS) {
        const int row = e / S, st = e % S;
        oIdx[(rowBase + row) * S + st] = sIdxAll[row * 8 + st];
    }

    // ---- per-CTA loss partial + last-CTA deterministic reduce ----
    #pragma unroll
    for (int off = 16; off; off >>= 1)
        lsum += __shfl_down_sync(0xffffffffu, lsum, off);
    if (lane == 0) sRed[w] = lsum;
    __syncthreads();
    if (tid == 0) {
        float tt = 0.f;
        #pragma unroll
        for (int i = 0; i < NWARP; ++i) tt += sRed[i];
        g_part[blockIdx.x] = tt;
        __threadfence();
        const unsigned ticket = atomicAdd(&g_cnt, 1u);
        sLast = (ticket == (unsigned)gridDim.x - 1u) ? 1 : 0;
    }
    __syncthreads();

    if (sLast) {
        __threadfence();
        const int nPart = gridDim.x;
        float ssum = 0.f;
        for (int i = tid; i < nPart; i += THREADS) ssum += g_part[i];
        #pragma unroll
        for (int off = 16; off; off >>= 1)
            ssum += __shfl_down_sync(0xffffffffu, ssum, off);
        if (lane == 0) sRed[w] = ssum;
        __syncthreads();
        if (tid == 0) {
            float tt = 0.f;
            #pragma unroll
            for (int i = 0; i < NWARP; ++i) tt += sRed[i];
            const float scale = 2.f / ((float)S * (float)N * (float)D);
            out[(size_t)N * D] = tt * scale;
            g_cnt = 0;                   // reset for next graph replay
        }
    }
}

extern "C" void kernel_launch(void* const* d_in, const int* in_sizes, int n_in,
                              void* d_out, int out_size)
{
    const float* x   = (const float*)d_in[0];
    const float* cbs = (const float*)d_in[1];
    float* out = (float*)d_out;

    const int N = in_sizes[0] / D;              // 262144
    const int S = in_sizes[1] / (C * D);        // 4
    const int nBlocks = N / ROWS;               // 2048

    cudaFuncSetAttribute(rvq_kernel, cudaFuncAttributeMaxDynamicSharedMemorySize,
                         SMEM_BYTES);
    rvq_kernel<<<nBlocks, THREADS, SMEM_BYTES>>>(x, cbs, out, N, S);
}

// round 14
// speedup vs baseline: 1.8470x; 1.0002x over previous
#include <cuda_runtime.h>

// Residual VQ via 3xTF32 tensor-core MMA (mma.sync.m16n8k8, mask split).
// hi = x & 0xFFFFE000 (exactly tf32), lo = x - hi (exact fp32, HW-truncated).
// Term-major MMA order (accumulator reuse distance 8) + B loaded RAW once per
// k-step (hi/lo derived in registers: 1 LOP3 / 1 FADD) -> 16 fewer LDS per kt.
// Rescue: fp64 full rescan when top-2 gap < 2e-3, 4-way ILP DFMA chains.
// Output (float32): x_q [N*128], mean_loss [1], indices [N*S].

#define D        128
#define C        256
#define ROWS     128
#define THREADS  1024
#define NWARP    32
#define MAXGRID  4096
#define EPS_GAP  2e-3f
#define LDA      132            // padded row stride (floats)

__device__ float        g_part[MAXGRID];
__device__ unsigned int g_cnt = 0;

// dynamic smem (floats)
#define OFF_A    0
#define OFF_B    (OFF_A + ROWS*LDA)
#define OFF_CN   (OFF_B + C*LDA)
#define OFF_PB1  (OFF_CN + 256)
#define OFF_PB2  (OFF_PB1 + 1024)
#define OFF_PI1  (OFF_PB2 + 1024)
#define OFF_IDX  (OFF_PI1 + 1024)
#define OFF_IALL (OFF_IDX + 128)
#define OFF_RED  (OFF_IALL + 128*8)
#define OFF_CNT  (OFF_RED + 32)
#define OFF_LIST (OFF_CNT + 1)
#define SMEM_FLOATS (OFF_LIST + 128)
#define SMEM_BYTES  (SMEM_FLOATS * 4 + 64)

#define MMA_TF32(c0,c1,c2,c3,a0,a1,a2,a3,b0,b1) \
    asm volatile("mma.sync.aligned.m16n8k8.row.col.f32.tf32.tf32.f32 " \
                 "{%0,%1,%2,%3},{%4,%5,%6,%7},{%8,%9},{%0,%1,%2,%3};" \
                 : "+f"(c0), "+f"(c1), "+f"(c2), "+f"(c3) \
                 : "r"(a0), "r"(a1), "r"(a2), "r"(a3), "r"(b0), "r"(b1))

__device__ __forceinline__ void split_tf32(float x, unsigned& hi, unsigned& lo) {
    hi = __float_as_uint(x) & 0xFFFFE000u;
    lo = __float_as_uint(x - __uint_as_float(hi));
}

__global__ void __launch_bounds__(THREADS, 1)
rvq_kernel(const float* __restrict__ x, const float* __restrict__ cbs,
           float* __restrict__ out, int N, int S)
{
    extern __shared__ float sm[];
    float* A       = sm + OFF_A;            // residual [row][k], stride 132
    float* B       = sm + OFF_B;            // codebook [code][k], stride 132
    float* cnorm   = sm + OFF_CN;
    float* pB1     = sm + OFF_PB1;          // partial best  [row*8 + ct]
    float* pB2     = sm + OFF_PB2;          // partial 2nd   [row*8 + ct]
    int*   pI1     = (int*)(sm + OFF_PI1);  // partial index [row*8 + ct]
    int*   sIdx    = (int*)(sm + OFF_IDX);
    float* sIdxAll = sm + OFF_IALL;
    float* sRed    = sm + OFF_RED;
    int*   sCnt    = (int*)(sm + OFF_CNT);
    int*   sList   = (int*)(sm + OFF_LIST);
    __shared__ int sLast;

    const int tid  = threadIdx.x;
    const int lane = tid & 31;
    const int w    = tid >> 5;       // 0..31
    const int g    = lane >> 2;      // mma group (0..7)
    const int t    = lane & 3;       // thread-in-group (0..3)
    const long long rowBase = (long long)blockIdx.x * ROWS;

    const int rt = w & 3;            // row tile: rows [rt*32, rt*32+32)
    const int ct = w >> 2;           // code tile: codes [ct*32, ct*32+32)
    const int arow = rt * 32 + g;

    // ---- load x tile into A: warp w -> rows [4w, 4w+4) ----
    {
        const int r8 = lane >> 3, f = lane & 7;
        const int row = 4 * w + r8;
        #pragma unroll
        for (int j = 0; j < 4; ++j) {
            const int k = j * 32 + f * 4;
            *(float4*)(A + row * LDA + k) =
                *(const float4*)(x + (rowBase + row) * D + k);
        }
    }

    float lsum = 0.f;

    for (int s = 0; s < S; ++s) {
        __syncthreads();             // previous stage done with B
        if (tid == 0) *sCnt = 0;

        // ---- codebook stage s -> B + cnorm (fixed-tree reduce over 8 lanes) ----
        {
            const float* cb = cbs + (size_t)s * C * D;
            const int r8 = lane >> 3, f = lane & 7;
            #pragma unroll
            for (int i = 0; i < 2; ++i) {
                const int code = 8 * w + 4 * i + r8;
                float psum = 0.f;
                #pragma unroll
                for (int j = 0; j < 4; ++j) {
                    const int k = j * 32 + f * 4;
                    const float4 v = *(const float4*)(cb + code * D + k);
                    *(float4*)(B + code * LDA + k) = v;
                    psum += v.x * v.x + v.y * v.y + v.z * v.z + v.w * v.w;
                }
                psum += __shfl_down_sync(0xffffffffu, psum, 4);
                psum += __shfl_down_sync(0xffffffffu, psum, 2);
                psum += __shfl_down_sync(0xffffffffu, psum, 1);
                if (f == 0) cnorm[code] = psum;
            }
        }
        __syncthreads();

        // ---- 3xTF32 MMA, term-major issue order, B loaded raw once per kt ----
        float acc[2][4][4];
        #pragma unroll
        for (int h = 0; h < 2; ++h)
            #pragma unroll
            for (int n = 0; n < 4; ++n)
                #pragma unroll
                for (int q = 0; q < 4; ++q) acc[h][n][q] = 0.f;

        #pragma unroll 2
        for (int kt = 0; kt < 16; ++kt) {
            const int kb = kt * 8;
            unsigned afh[2][4], afl[2][4];
            #pragma unroll
            for (int h = 0; h < 2; ++h) {
                const int r0 = arow + 16 * h;
                split_tf32(A[ r0      * LDA + kb + t],     afh[h][0], afl[h][0]);
                split_tf32(A[(r0 + 8) * LDA + kb + t],     afh[h][1], afl[h][1]);
                split_tf32(A[ r0      * LDA + kb + t + 4], afh[h][2], afl[h][2]);
                split_tf32(A[(r0 + 8) * LDA + kb + t + 4], afh[h][3], afl[h][3]);
            }
            // B raw, loaded once (held in regs through the kt)
            unsigned braw[4][2];
            #pragma unroll
            for (int n = 0; n < 4; ++n) {
                const int code = ct * 32 + n * 8 + g;
                braw[n][0] = __float_as_uint(B[code * LDA + kb + t]);
                braw[n][1] = __float_as_uint(B[code * LDA + kb + t + 4]);
            }
            // term 0: Ahi x Bhi
            #pragma unroll
            for (int n = 0; n < 4; ++n) {
                const unsigned b0 = braw[n][0] & 0xFFFFE000u;
                const unsigned b1 = braw[n][1] & 0xFFFFE000u;
                MMA_TF32(acc[0][n][0], acc[0][n][1], acc[0][n][2], acc[0][n][3],
                         afh[0][0], afh[0][1], afh[0][2], afh[0][3], b0, b1);
                MMA_TF32(acc[1][n][0], acc[1][n][1], acc[1][n][2], acc[1][n][3],
                         afh[1][0], afh[1][1], afh[1][2], afh[1][3], b0, b1);
            }
            // term 1: Ahi x Blo
            #pragma unroll
            for (int n = 0; n < 4; ++n) {
                const unsigned h0 = braw[n][0] & 0xFFFFE000u;
                const unsigned h1 = braw[n][1] & 0xFFFFE000u;
                const unsigned bl0 = __float_as_uint(
                    __uint_as_float(braw[n][0]) - __uint_as_float(h0));
                const unsigned bl1 = __float_as_uint(
                    __uint_as_float(braw[n][1]) - __uint_as_float(h1));
                MMA_TF32(acc[0][n][0], acc[0][n][1], acc[0][n][2], acc[0][n][3],
                         afh[0][0], afh[0][1], afh[0][2], afh[0][3], bl0, bl1);
                MMA_TF32(acc[1][n][0], acc[1][n][1], acc[1][n][2], acc[1][n][3],
                         afh[1][0], afh[1][1], afh[1][2], afh[1][3], bl0, bl1);
            }
            // term 2: Alo x Bhi
            #pragma unroll
            for (int n = 0; n < 4; ++n) {
                const unsigned b0 = braw[n][0] & 0xFFFFE000u;
                const unsigned b1 = braw[n][1] & 0xFFFFE000u;
                MMA_TF32(acc[0][n][0], acc[0][n][1], acc[0][n][2], acc[0][n][3],
                         afl[0][0], afl[0][1], afl[0][2], afl[0][3], b0, b1);
                MMA_TF32(acc[1][n][0], acc[1][n][1], acc[1][n][2], acc[1][n][3],
                         afl[1][0], afl[1][1], afl[1][2], afl[1][3], b0, b1);
            }
        }

        // ---- per-(row, code-tile) top-2 partials ----
        #pragma unroll
        for (int h = 0; h < 2; ++h) {
            #pragma unroll
            for (int rr = 0; rr < 2; ++rr) {        // row = arow + 16h + 8rr
                float b1v = 3.4e38f, b2v = 3.4e38f;
                int   i1  = 0;
                #pragma unroll
                for (int n = 0; n < 4; ++n) {
                    const int code0 = ct * 32 + n * 8 + 2 * t;
                    const float s0 = fmaf(-2.f, acc[h][n][rr * 2 + 0], cnorm[code0]);
                    const float s1 = fmaf(-2.f, acc[h][n][rr * 2 + 1], cnorm[code0 + 1]);
                    if (s0 < b1v) { b2v = b1v; b1v = s0; i1 = code0; }
                    else if (s0 < b2v) b2v = s0;
                    if (s1 < b1v) { b2v = b1v; b1v = s1; i1 = code0 + 1; }
                    else if (s1 < b2v) b2v = s1;
                }
                #pragma unroll
                for (int off = 1; off <= 2; off <<= 1) {
                    const float ov1 = __shfl_xor_sync(0xffffffffu, b1v, off);
                    const int   oi  = __shfl_xor_sync(0xffffffffu, i1, off);
                    const float ov2 = __shfl_xor_sync(0xffffffffu, b2v, off);
                    const float m2  = fminf(fmaxf(b1v, ov1), fminf(b2v, ov2));
                    if (ov1 < b1v || (ov1 == b1v && oi < i1)) { b1v = ov1; i1 = oi; }
                    b2v = m2;
                }
                if (t == 0) {
                    const int row = arow + 16 * h + 8 * rr;
                    pB1[row * 8 + ct] = b1v;
                    pB2[row * 8 + ct] = b2v;
                    pI1[row * 8 + ct] = i1;
                }
            }
        }
        __syncthreads();

        // ---- merge 8 code-tile partials per row; nominate fp64 rescans ----
        if (w < 4) {
            const int row = w * 32 + lane;
            float b1v = 3.4e38f, b2v = 3.4e38f;
            int   i1  = 0;
            #pragma unroll
            for (int c = 0; c < 8; ++c) {
                const float ov1 = pB1[row * 8 + c];
                const float ov2 = pB2[row * 8 + c];
                const int   oi  = pI1[row * 8 + c];
                const float m2  = fminf(fmaxf(b1v, ov1), fminf(b2v, ov2));
                if (ov1 < b1v || (ov1 == b1v && oi < i1)) { b1v = ov1; i1 = oi; }
                b2v = m2;
            }
            if (b2v - b1v < EPS_GAP) {
                const int pos = atomicAdd(sCnt, 1);
                sList[pos] = row;
            } else {
                sIdx[row] = i1;
                sIdxAll[row * 8 + s] = (float)i1;
            }
        }
        __syncthreads();

        // ---- fp64 full rescan for near-tie rows (rare; 4-way ILP chain) ----
        {
            const int cnt = *sCnt;
            for (int e = w; e < cnt; e += NWARP) {
                const int row = sList[e];
                double d1 = 1e300; int di = 0x7fffffff;
                #pragma unroll
                for (int cc = 0; cc < 8; ++cc) {
                    const int code = cc * 32 + lane;
                    const float* Bc  = B + code * LDA;
                    const float* Arf = A + row * LDA;
                    double q0 = 0.0, q1 = 0.0, q2 = 0.0, q3 = 0.0;
                    for (int k = 0; k < D; k += 4) {
                        const double f0 = (double)Arf[k]     - (double)Bc[k];
                        const double f1 = (double)Arf[k + 1] - (double)Bc[k + 1];
                        const double f2 = (double)Arf[k + 2] - (double)Bc[k + 2];
                        const double f3 = (double)Arf[k + 3] - (double)Bc[k + 3];
                        q0 = fma(f0, f0, q0);
                        q1 = fma(f1, f1, q1);
                        q2 = fma(f2, f2, q2);
                        q3 = fma(f3, f3, q3);
                    }
                    const double dsum = ((q0 + q1) + q2) + q3;
                    if (dsum < d1 || (dsum == d1 && code < di)) { d1 = dsum; di = code; }
                }
                #pragma unroll
                for (int off = 16; off; off >>= 1) {
                    const double ov = __shfl_xor_sync(0xffffffffu, d1, off);
                    const int    oi = __shfl_xor_sync(0xffffffffu, di, off);
                    if (ov < d1 || (ov == d1 && oi < di)) { d1 = ov; di = oi; }
                }
                if (lane == 0) {
                    sIdx[row] = di;
                    sIdxAll[row * 8 + s] = (float)di;
                }
            }
        }
        __syncthreads();

        // ---- residual update + loss: warp w -> rows [4w, 4w+4) ----
        {
            const int r8 = lane >> 3, f = lane & 7;
            const int row = 4 * w + r8;
            const int idx = sIdx[row];
            #pragma unroll
            for (int j = 0; j < 4; ++j) {
                const int k = j * 32 + f * 4;
                float4 rv = *(const float4*)(A + row * LDA + k);
                const float4 cv = *(const float4*)(B + idx * LDA + k);
                rv.x -= cv.x; rv.y -= cv.y; rv.z -= cv.z; rv.w -= cv.w;
                *(float4*)(A + row * LDA + k) = rv;
                lsum += rv.x * rv.x + rv.y * rv.y + rv.z * rv.z + rv.w * rv.w;
            }
        }
    }
    __syncthreads();

    // ---- x_q = x - final residual ----
    {
        const int r8 = lane >> 3, f = lane & 7;
        const int row = 4 * w + r8;
        #pragma unroll
        for (int j = 0; j < 4; ++j) {
            const int k = j * 32 + f * 4;
            const float4 xv = *(const float4*)(x + (rowBase + row) * D + k);
            const float4 rv = *(const float4*)(A + row * LDA + k);
            float4 o;
            o.x = xv.x - rv.x; o.y = xv.y - rv.y;
            o.z = xv.z - rv.z; o.w = xv.w - rv.w;
            *(float4*)(out + (rowBase + row) * D + k) = o;
        }
    }

    // ---- indices (float) ----
    float* oIdx = out + (size_t)N * D + 1;
    for (int e = tid; e < ROWS * S; e += THREADS) {
        const int row = e / S, st = e % S;
        oIdx[(rowBase + row) * S + st] = sIdxAll[row * 8 + st];
    }

    // ---- per-CTA loss partial + last-CTA deterministic reduce ----
    #pragma unroll
    for (int off = 16; off; off >>= 1)
        lsum += __shfl_down_sync(0xffffffffu, lsum, off);
    if (lane == 0) sRed[w] = lsum;
    __syncthreads();
    if (tid == 0) {
        float tt = 0.f;
        #pragma unroll
        for (int i = 0; i < NWARP; ++i) tt += sRed[i];
        g_part[blockIdx.x] = tt;
        __threadfence();
        const unsigned ticket = atomicAdd(&g_cnt, 1u);
        sLast = (ticket == (unsigned)gridDim.x - 1u) ? 1 : 0;
    }
    __syncthreads();

    if (sLast) {
        __threadfence();
        const int nPart = gridDim.x;
        float ssum = 0.f;
        for (int i = tid; i < nPart; i += THREADS) ssum += g_part[i];
        #pragma unroll
        for (int off = 16; off; off >>= 1)
            ssum += __shfl_down_sync(0xffffffffu, ssum, off);
        if (lane == 0) sRed[w] = ssum;
        __syncthreads();
        if (tid == 0) {
            float tt = 0.f;
            #pragma unroll
            for (int i = 0; i < NWARP; ++i) tt += sRed[i];
            const float scale = 2.f / ((float)S * (float)N * (float)D);
            out[(size_t)N * D] = tt * scale;
            g_cnt = 0;                   // reset for next graph replay
        }
    }
}

extern "C" void kernel_launch(void* const* d_in, const int* in_sizes, int n_in,
                              void* d_out, int out_size)
{
    const float* x   = (const float*)d_in[0];
    const float* cbs = (const float*)d_in[1];
    float* out = (float*)d_out;

    const int N = in_sizes[0] / D;              // 262144
    const int S = in_sizes[1] / (C * D);        // 4
    const int nBlocks = N / ROWS;               // 2048

    cudaFuncSetAttribute(rvq_kernel, cudaFuncAttributeMaxDynamicSharedMemorySize,
                         SMEM_BYTES);
    rvq_kernel<<<nBlocks, THREADS, SMEM_BYTES>>>(x, cbs, out, N, S);
}